// round 5
// baseline (speedup 1.0000x reference)
#include <cuda_runtime.h>
#include <math.h>

// ---------------- Problem constants ----------------
#define BB   256      // batch
#define TT   64       // timesteps
#define INM  600      // input size
#define H    1000     // hidden
#define HP   1024     // padded hidden
#define NP   4096     // 4*HP gate columns (interleaved: col = 4*unit + gate)

// ---------------- Device scratch (static; no allocations allowed) ----------------
__device__ float g_WA1[INM * NP];       // x -> gates1        [600][4096]
__device__ float g_WB1[HP * NP];        // h1 -> gates1       [1024][4096]
__device__ float g_WC2[2 * HP * NP];    // [h1,h2] -> gates2  [2048][4096]
__device__ float g_W1T[2 * HP * NP];    // [h1,topic] -> m1   [2048][4096]
__device__ float g_W2T[NP * HP];        // m1 -> m2           [4096][1024]
__device__ float g_b1v[NP];             // folded lstm1 bias (interleaved)
__device__ float g_b2v[NP];             // folded lstm2 bias (interleaved)
__device__ float g_bl1[NP];             // b1 padded
__device__ float g_bl2[HP];             // b2 padded
__device__ float g_xproj[TT * BB * NP]; // precomputed x-projection (+bias1)
__device__ float g_h1[2][BB * HP];
__device__ float g_h2[2][BB * HP];
__device__ float g_c1[BB * HP];
__device__ float g_c2[BB * HP];
__device__ float g_F[BB * 2 * HP];      // [h1_final | topic] padded
__device__ float g_m1[BB * NP];
__device__ float g_m2[BB * HP];

// ---------------- Weight folding kernels ----------------
__global__ void k_foldWA1(const float* __restrict__ Wih1) {
    int idx = blockIdx.x * blockDim.x + threadIdx.x;
    if (idx >= INM * NP) return;
    int k = idx / NP, c = idx % NP, u = c >> 2, g = c & 3;
    g_WA1[idx] = (u < H) ? Wih1[(g * H + u) * 1600 + k] : 0.f;
}
__global__ void k_foldWB1(const float* __restrict__ Wih1, const float* __restrict__ Whh1) {
    int idx = blockIdx.x * blockDim.x + threadIdx.x;
    if (idx >= HP * NP) return;
    int k = idx / NP, c = idx % NP, u = c >> 2, g = c & 3;
    float v = 0.f;
    if (u < H && k < H) v = Wih1[(g * H + u) * 1600 + 600 + k] + Whh1[(g * H + u) * H + k];
    g_WB1[idx] = v;
}
__global__ void k_foldWC2(const float* __restrict__ Wih2, const float* __restrict__ Whh2) {
    int idx = blockIdx.x * blockDim.x + threadIdx.x;
    if (idx >= 2 * HP * NP) return;
    int k = idx / NP, c = idx % NP, u = c >> 2, g = c & 3;
    float v = 0.f;
    if (u < H) {
        if (k < H) v = Wih2[(g * H + u) * 2600 + 600 + k];                 // h1 part
        else if (k >= HP && k < HP + H) {
            int kk = k - HP;                                               // h2 part
            v = Wih2[(g * H + u) * 2600 + 1600 + kk] + Whh2[(g * H + u) * H + kk];
        }
    }
    g_WC2[idx] = v;
}
__global__ void k_foldBias(const float* __restrict__ bih1, const float* __restrict__ bhh1,
                           const float* __restrict__ bih2, const float* __restrict__ bhh2) {
    int c = blockIdx.x * blockDim.x + threadIdx.x;
    if (c >= NP) return;
    int u = c >> 2, g = c & 3;
    g_b1v[c] = (u < H) ? bih1[g * H + u] + bhh1[g * H + u] : 0.f;
    g_b2v[c] = (u < H) ? bih2[g * H + u] + bhh2[g * H + u] : 0.f;
}
__global__ void k_foldW1T(const float* __restrict__ W1) {
    int idx = blockIdx.x * blockDim.x + threadIdx.x;
    if (idx >= 2 * HP * NP) return;
    int k = idx / NP, n = idx % NP;
    float v = 0.f;
    if (n < 4000) {
        if (k < H) v = W1[n * 2000 + k];                       // h1 part
        else if (k >= HP && k < HP + H) v = W1[n * 2000 + 1000 + (k - HP)];  // topic part
    }
    g_W1T[idx] = v;
}
__global__ void k_foldW2T(const float* __restrict__ W2) {
    int idx = blockIdx.x * blockDim.x + threadIdx.x;
    if (idx >= NP * HP) return;
    int k = idx / HP, n = idx % HP;
    g_W2T[idx] = (k < 4000 && n < H) ? W2[n * 4000 + k] : 0.f;
}
__global__ void k_foldLinB(const float* __restrict__ b1, const float* __restrict__ b2) {
    int i = blockIdx.x * blockDim.x + threadIdx.x;
    if (i < NP) g_bl1[i] = (i < 4000) ? b1[i] : 0.f;
    if (i < HP) g_bl2[i] = (i < H) ? b2[i] : 0.f;
}
__global__ void k_zeroState() {
    int idx = blockIdx.x * blockDim.x + threadIdx.x;
    if (idx >= BB * HP) return;
    g_h1[0][idx] = 0.f; g_h2[0][idx] = 0.f; g_c1[idx] = 0.f; g_c2[idx] = 0.f;
}

// ---------------- Generic tiled SGEMM with fused epilogues ----------------
// C[M,N] = A[M,K] @ B[K,N] (+ epilogue)
// AMODE: 0 = row-major A (lda); 1 = input-tensor map r=(t*256+m) -> input[m][t][k];
//        2 = split: k<HP from A (h1), k>=HP from A2 (h2), both lda=HP
// EPI:   0 = C[r,c] = acc + bias[c]
//        1 = LSTM with pre-matrix addend (Xproj row, stride NP) -> cSt/hOut
//        2 = LSTM with bias[c] addend -> cSt/hOut
// Register double-buffering: tile k+1 is fetched from global into registers
// while tile k is being computed from shared, hiding L2 latency (234-262 cyc)
// behind the ~2k-cycle FFMA phase.
__device__ __forceinline__ float sigm(float x) { return 1.f / (1.f + expf(-x)); }

template<int BM, int BN, int BK, int TM, int TN, int AMODE, int EPI>
__global__ void gemm_k(const float* __restrict__ A, const float* __restrict__ A2,
                       const float* __restrict__ Bm, const float* __restrict__ pre,
                       const float* __restrict__ bias, float* __restrict__ C,
                       float* __restrict__ cSt, float* __restrict__ hOut,
                       int K, int lda, int ldb, int ldc) {
    // BM+4 pad keeps each As row 16B-aligned (row stride multiple of 16B) so the
    // TM-consecutive fragment loads vectorize to LDS.128 while skewing banks.
    __shared__ float As[BK][BM + 4];
    __shared__ float Bs[BK][BN];
    const int NT = (BM / TM) * (BN / TN);   // == blockDim.x (256)
    const int LA = (BM * BK) / 256;         // A elems per thread per tile
    const int LB = (BK * BN) / 256;         // B elems per thread per tile
    const int tid = threadIdx.x;
    const int tx = tid % (BN / TN);
    const int ty = tid / (BN / TN);
    const int rowBase = blockIdx.y * BM;
    const int colBase = blockIdx.x * BN;

    float acc[TM][TN];
#pragma unroll
    for (int i = 0; i < TM; i++)
#pragma unroll
        for (int j = 0; j < TN; j++) acc[i][j] = 0.f;

    float ra[LA], rb[LB];

    // ---- global->register tile fetch (k0 = tile base along K) ----
    auto fetch = [&](int k0) {
#pragma unroll
        for (int i = 0; i < LA; i++) {
            int e = tid + i * NT;
            int rr = e / BK, kk = e % BK;
            int gr = rowBase + rr, gk = k0 + kk;
            float v;
            if (AMODE == 0)      v = A[gr * lda + gk];
            else if (AMODE == 1) v = A[(gr & 255) * (TT * INM) + (gr >> 8) * INM + gk];
            else                 v = (gk < HP) ? A[gr * HP + gk] : A2[gr * HP + (gk - HP)];
            ra[i] = v;
        }
#pragma unroll
        for (int i = 0; i < LB; i++) {
            int e = tid + i * NT;
            int kk = e / BN, cc = e % BN;
            rb[i] = Bm[(k0 + kk) * ldb + colBase + cc];
        }
    };
    // ---- register->shared store ----
    auto stage = [&]() {
#pragma unroll
        for (int i = 0; i < LA; i++) {
            int e = tid + i * NT;
            As[e % BK][e / BK] = ra[i];
        }
#pragma unroll
        for (int i = 0; i < LB; i++) {
            int e = tid + i * NT;
            Bs[e / BN][e % BN] = rb[i];
        }
    };

    fetch(0);                      // prologue
    for (int k0 = 0; k0 < K; k0 += BK) {
        stage();
        __syncthreads();
        if (k0 + BK < K) fetch(k0 + BK);   // prefetch next tile during compute
#pragma unroll
        for (int kk = 0; kk < BK; kk++) {
            float a[TM], b[TN];
#pragma unroll
            for (int i = 0; i < TM; i++) a[i] = As[kk][ty * TM + i];
#pragma unroll
            for (int j = 0; j < TN; j++) b[j] = Bs[kk][tx * TN + j];
#pragma unroll
            for (int i = 0; i < TM; i++)
#pragma unroll
                for (int j = 0; j < TN; j++) acc[i][j] += a[i] * b[j];
        }
        __syncthreads();
    }

    if (EPI == 0) {
#pragma unroll
        for (int i = 0; i < TM; i++) {
            int r = rowBase + ty * TM + i;
#pragma unroll
            for (int j = 0; j < TN; j++) {
                int c = colBase + tx * TN + j;
                C[r * ldc + c] = acc[i][j] + bias[c];
            }
        }
    } else {
        // LSTM epilogue: TN multiple of 4; cols tx*TN.. are 4-aligned gate groups
#pragma unroll
        for (int i = 0; i < TM; i++) {
            int r = rowBase + ty * TM + i;
#pragma unroll
            for (int q = 0; q < TN / 4; q++) {
                int c0 = colBase + tx * TN + q * 4;
                float gi = acc[i][q * 4 + 0], gf = acc[i][q * 4 + 1];
                float gg = acc[i][q * 4 + 2], go = acc[i][q * 4 + 3];
                if (EPI == 1) {
                    const float* p = pre + r * NP + c0;
                    gi += p[0]; gf += p[1]; gg += p[2]; go += p[3];
                } else {
                    gi += bias[c0]; gf += bias[c0 + 1]; gg += bias[c0 + 2]; go += bias[c0 + 3];
                }
                int u = c0 >> 2;
                float cold = cSt[r * HP + u];
                float I = sigm(gi), Fg = sigm(gf), G = tanhf(gg), O = sigm(go);
                float cn = Fg * cold + I * G;
                float hn = O * tanhf(cn);
                cSt[r * HP + u] = cn;
                hOut[r * HP + u] = hn;
            }
        }
    }
}

// ---------------- Tail kernels ----------------
__global__ void k_buildF(const float* __restrict__ h1fin) {
    int idx = blockIdx.x * blockDim.x + threadIdx.x;
    if (idx >= BB * 2 * HP) return;
    int m = idx / (2 * HP), k = idx % (2 * HP);
    g_F[idx] = (k < HP) ? h1fin[m * HP + k] : 0.f;
}
__global__ void k_scatterTopic(const int* __restrict__ hidx) {
    int m = threadIdx.x;
    if (m >= BB) return;
#pragma unroll
    for (int j = 0; j < 5; j++) {
        int u = hidx[m * 5 + j];
        g_F[m * 2 * HP + HP + u] = 1.0f;
    }
}
__global__ void k_softmax(float* __restrict__ out, int out_size) {
    int j = blockIdx.x;          // column 0..999
    int r = threadIdx.x;         // row 0..255
    __shared__ float sm[256];
    float v = g_m2[r * HP + j];
    sm[r] = v; __syncthreads();
    for (int s = 128; s > 0; s >>= 1) { if (r < s) sm[r] = fmaxf(sm[r], sm[r + s]); __syncthreads(); }
    float mx = sm[0]; __syncthreads();
    float e = expf(v - mx);
    sm[r] = e; __syncthreads();
    for (int s = 128; s > 0; s >>= 1) { if (r < s) sm[r] += sm[r + s]; __syncthreads(); }
    float p = e / sm[0];
    int off = r * 1000 + j;
    if (off < out_size) out[off] = p;
}
__global__ void k_copyStates(float* __restrict__ out, int out_size) {
    int idx = blockIdx.x * blockDim.x + threadIdx.x;
    if (idx >= 4 * BB * H) return;
    int which = idx / (BB * H), rem = idx % (BB * H);
    int m = rem / H, u = rem % H;
    const float* src;
    if (which == 0)      src = g_h1[0];
    else if (which == 1) src = g_c1;
    else if (which == 2) src = g_h2[0];
    else                 src = g_c2;
    int off = BB * H + idx;   // after softmax block
    if (off < out_size) out[off] = src[m * HP + u];
}

// ---------------- Launch ----------------
extern "C" void kernel_launch(void* const* d_in, const int* in_sizes, int n_in,
                              void* d_out, int out_size) {
    const float* input = (const float*)d_in[0];
    const int*   hidx  = (const int*)d_in[1];
    const float* Wih1  = (const float*)d_in[2];
    const float* Whh1  = (const float*)d_in[3];
    const float* bih1  = (const float*)d_in[4];
    const float* bhh1  = (const float*)d_in[5];
    const float* Wih2  = (const float*)d_in[6];
    const float* Whh2  = (const float*)d_in[7];
    const float* bih2  = (const float*)d_in[8];
    const float* bhh2  = (const float*)d_in[9];
    const float* W1    = (const float*)d_in[10];
    const float* b1    = (const float*)d_in[11];
    const float* W2    = (const float*)d_in[12];
    const float* b2    = (const float*)d_in[13];
    float* out = (float*)d_out;

    // device pointers to scratch symbols (pure address lookups; no stream ops,
    // safe under graph capture)
    float *pWA1, *pWB1, *pWC2, *pW1T, *pW2T, *pb1v, *pb2v, *pbl1, *pbl2;
    float *pxp, *ph1, *ph2, *pc1, *pc2, *pF, *pm1, *pm2;
    cudaGetSymbolAddress((void**)&pWA1, g_WA1);
    cudaGetSymbolAddress((void**)&pWB1, g_WB1);
    cudaGetSymbolAddress((void**)&pWC2, g_WC2);
    cudaGetSymbolAddress((void**)&pW1T, g_W1T);
    cudaGetSymbolAddress((void**)&pW2T, g_W2T);
    cudaGetSymbolAddress((void**)&pb1v, g_b1v);
    cudaGetSymbolAddress((void**)&pb2v, g_b2v);
    cudaGetSymbolAddress((void**)&pbl1, g_bl1);
    cudaGetSymbolAddress((void**)&pbl2, g_bl2);
    cudaGetSymbolAddress((void**)&pxp,  g_xproj);
    cudaGetSymbolAddress((void**)&ph1,  g_h1);
    cudaGetSymbolAddress((void**)&ph2,  g_h2);
    cudaGetSymbolAddress((void**)&pc1,  g_c1);
    cudaGetSymbolAddress((void**)&pc2,  g_c2);
    cudaGetSymbolAddress((void**)&pF,   g_F);
    cudaGetSymbolAddress((void**)&pm1,  g_m1);
    cudaGetSymbolAddress((void**)&pm2,  g_m2);

    const int TH = 256;
    // 1) fold weights
    k_foldWA1<<<(INM * NP + TH - 1) / TH, TH>>>(Wih1);
    k_foldWB1<<<(HP * NP + TH - 1) / TH, TH>>>(Wih1, Whh1);
    k_foldWC2<<<(2 * HP * NP + TH - 1) / TH, TH>>>(Wih2, Whh2);
    k_foldBias<<<(NP + TH - 1) / TH, TH>>>(bih1, bhh1, bih2, bhh2);
    k_foldW1T<<<(2 * HP * NP + TH - 1) / TH, TH>>>(W1);
    k_foldW2T<<<(NP * HP + TH - 1) / TH, TH>>>(W2);
    k_foldLinB<<<(NP + TH - 1) / TH, TH>>>(b1, b2);
    k_zeroState<<<(BB * HP + TH - 1) / TH, TH>>>();

    // 2) Xproj = input @ WA1 + b1v   (M=16384, N=4096, K=600)
    {
        dim3 grid(NP / 64, (TT * BB) / 128);
        gemm_k<128, 64, 8, 8, 4, 1, 0><<<grid, TH>>>(
            input, nullptr, pWA1, nullptr, pb1v, pxp, nullptr, nullptr,
            INM, 0, NP, NP);
    }

    // 3) recurrent steps
    float* h1buf[2] = { ph1, ph1 + BB * HP };
    float* h2buf[2] = { ph2, ph2 + BB * HP };
    for (int t = 0; t < TT; t++) {
        int p = t & 1;
        dim3 grid(NP / 128, BB / 64);
        // LSTM1: gates = Xproj[t] + h1_old @ WB1
        gemm_k<64, 128, 16, 4, 8, 0, 1><<<grid, TH>>>(
            h1buf[p], nullptr, pWB1, pxp + (size_t)t * BB * NP, nullptr,
            nullptr, pc1, h1buf[1 - p], HP, HP, NP, 0);
        // LSTM2: gates = b2v + [h1_new, h2_old] @ WC2
        gemm_k<64, 128, 16, 4, 8, 2, 2><<<grid, TH>>>(
            h1buf[1 - p], h2buf[p], pWC2, nullptr, pb2v,
            nullptr, pc2, h2buf[1 - p], 2 * HP, HP, NP, 0);
    }
    // after 64 steps (even count), final states are in buffer 0

    // 4) tail: F = [h1_final | topic]; m1 = F@W1T + b1; m2 = m1@W2T + b2
    k_buildF<<<(BB * 2 * HP + TH - 1) / TH, TH>>>(h1buf[0]);
    k_scatterTopic<<<1, TH>>>(hidx);
    {
        dim3 grid(NP / 128, BB / 64);
        gemm_k<64, 128, 16, 4, 8, 0, 0><<<grid, TH>>>(
            pF, nullptr, pW1T, nullptr, pbl1, pm1, nullptr, nullptr,
            2 * HP, 2 * HP, NP, NP);
    }
    {
        dim3 grid(HP / 64, BB / 32);
        gemm_k<32, 64, 16, 2, 4, 0, 0><<<grid, TH>>>(
            pm1, nullptr, pW2T, nullptr, pbl2, pm2, nullptr, nullptr,
            NP, NP, HP, HP);
    }

    // 5) softmax over batch (axis 0) + emit states
    k_softmax<<<1000, 256>>>(out, out_size);
    k_copyStates<<<(4 * BB * H + TH - 1) / TH, TH>>>(out, out_size);
}

// round 8
// speedup vs baseline: 2.1519x; 2.1519x over previous
#include <cuda_runtime.h>
#include <cuda_bf16.h>
#include <math.h>
#include <stdint.h>

// ---------------- Problem constants ----------------
#define BB   256      // batch
#define TT   64       // timesteps
#define INM  600      // input size
#define KA   640      // padded input K (mult of 32)
#define H    1000     // hidden
#define HP   1024     // padded hidden
#define NP   4096     // 4*HP gate columns (interleaved: col = 4*unit + gate)

// ---------------- Device scratch (static; no allocations allowed) ----------------
// bf16 split weights, TRANSPOSED [N][K] for mma B-fragment staging
__device__ __nv_bfloat16 g_WA1h[NP * KA],     g_WA1l[NP * KA];      // x -> gates1
__device__ __nv_bfloat16 g_WB1h[NP * HP],     g_WB1l[NP * HP];      // h1 -> gates1
__device__ __nv_bfloat16 g_WC2h[NP * 2 * HP], g_WC2l[NP * 2 * HP];  // [h1,h2] -> gates2
__device__ float g_W1T[2 * HP * NP];    // fp32 tail: [h1,topic] -> m1
__device__ float g_W2T[NP * HP];        // fp32 tail: m1 -> m2
__device__ float g_b1v[NP], g_b2v[NP], g_bl1[NP], g_bl2[HP];
__device__ __nv_bfloat16 g_ih[TT * BB * KA], g_il[TT * BB * KA];    // split input [t*256+m][KA]
__device__ float g_xproj[(size_t)TT * BB * NP];
__device__ float g_h1f[2][BB * HP], g_h2f[2][BB * HP], g_c1[BB * HP], g_c2[BB * HP];
__device__ __nv_bfloat16 g_h1bh[2][BB * HP], g_h1bl[2][BB * HP];
__device__ __nv_bfloat16 g_h2bh[2][BB * HP], g_h2bl[2][BB * HP];
__device__ float g_F[BB * 2 * HP], g_m1[BB * NP], g_m2[BB * HP];

__device__ __forceinline__ float sigm(float x) { return 1.f / (1.f + expf(-x)); }
__device__ __forceinline__ void bsplit(float v, __nv_bfloat16& h, __nv_bfloat16& l) {
    h = __float2bfloat16(v);
    l = __float2bfloat16(v - __bfloat162float(h));
}

// ---------------- Weight folding (bf16 split, transposed [N][K]) ----------------
__global__ void k_foldWA1b(const float* __restrict__ Wih1) {
    int idx = blockIdx.x * blockDim.x + threadIdx.x;
    if (idx >= NP * KA) return;
    int n = idx / KA, k = idx % KA, u = n >> 2, gt = n & 3;
    float v = (u < H && k < INM) ? Wih1[(gt * H + u) * 1600 + k] : 0.f;
    bsplit(v, g_WA1h[idx], g_WA1l[idx]);
}
__global__ void k_foldWB1b(const float* __restrict__ Wih1, const float* __restrict__ Whh1) {
    int idx = blockIdx.x * blockDim.x + threadIdx.x;
    if (idx >= NP * HP) return;
    int n = idx / HP, k = idx % HP, u = n >> 2, gt = n & 3;
    float v = 0.f;
    if (u < H && k < H) v = Wih1[(gt * H + u) * 1600 + 600 + k] + Whh1[(gt * H + u) * H + k];
    bsplit(v, g_WB1h[idx], g_WB1l[idx]);
}
__global__ void k_foldWC2b(const float* __restrict__ Wih2, const float* __restrict__ Whh2) {
    int idx = blockIdx.x * blockDim.x + threadIdx.x;
    if (idx >= NP * 2 * HP) return;
    int n = idx / (2 * HP), k = idx % (2 * HP), u = n >> 2, gt = n & 3;
    float v = 0.f;
    if (u < H) {
        if (k < HP) { if (k < H) v = Wih2[(gt * H + u) * 2600 + 600 + k]; }
        else { int kk = k - HP; if (kk < H) v = Wih2[(gt * H + u) * 2600 + 1600 + kk] + Whh2[(gt * H + u) * H + kk]; }
    }
    bsplit(v, g_WC2h[idx], g_WC2l[idx]);
}
__global__ void k_foldBias(const float* __restrict__ bih1, const float* __restrict__ bhh1,
                           const float* __restrict__ bih2, const float* __restrict__ bhh2) {
    int c = blockIdx.x * blockDim.x + threadIdx.x;
    if (c >= NP) return;
    int u = c >> 2, gt = c & 3;
    g_b1v[c] = (u < H) ? bih1[gt * H + u] + bhh1[gt * H + u] : 0.f;
    g_b2v[c] = (u < H) ? bih2[gt * H + u] + bhh2[gt * H + u] : 0.f;
}
__global__ void k_foldW1T(const float* __restrict__ W1) {
    int idx = blockIdx.x * blockDim.x + threadIdx.x;
    if (idx >= 2 * HP * NP) return;
    int k = idx / NP, n = idx % NP;
    float v = 0.f;
    if (n < 4000) {
        if (k < H) v = W1[n * 2000 + k];
        else if (k >= HP && k < HP + H) v = W1[n * 2000 + 1000 + (k - HP)];
    }
    g_W1T[idx] = v;
}
__global__ void k_foldW2T(const float* __restrict__ W2) {
    int idx = blockIdx.x * blockDim.x + threadIdx.x;
    if (idx >= NP * HP) return;
    int k = idx / HP, n = idx % HP;
    g_W2T[idx] = (k < 4000 && n < H) ? W2[n * 4000 + k] : 0.f;
}
__global__ void k_foldLinB(const float* __restrict__ b1, const float* __restrict__ b2) {
    int i = blockIdx.x * blockDim.x + threadIdx.x;
    if (i < NP) g_bl1[i] = (i < 4000) ? b1[i] : 0.f;
    if (i < HP) g_bl2[i] = (i < H) ? b2[i] : 0.f;
}
__global__ void k_zeroState() {
    int idx = blockIdx.x * blockDim.x + threadIdx.x;
    if (idx >= BB * HP) return;
    g_h1f[0][idx] = 0.f; g_h2f[0][idx] = 0.f; g_c1[idx] = 0.f; g_c2[idx] = 0.f;
    __nv_bfloat16 z = __float2bfloat16(0.f);
    g_h1bh[0][idx] = z; g_h1bl[0][idx] = z; g_h2bh[0][idx] = z; g_h2bl[0][idx] = z;
}
__global__ void k_splitInput(const float* __restrict__ input) {
    int idx = blockIdx.x * blockDim.x + threadIdx.x;
    if (idx >= TT * BB * KA) return;
    int r = idx / KA, k = idx % KA;
    int t = r >> 8, m = r & 255;  // r = t*256 + m
    float v = (k < INM) ? input[m * (TT * INM) + t * INM + k] : 0.f;
    bsplit(v, g_ih[idx], g_il[idx]);
}

// ---------------- split-bf16 tensor-core GEMM with fused LSTM epilogue ----------------
// C[M,N] = A[M,K] @ W[K,N], W stored transposed [N][K] bf16 (hi/lo).
// A stored row-major bf16 hi/lo (lda elements).
// AMODE: 0 = single A; 2 = k<HP from A(h1), k>=HP from A2(h2), both stride lda
// EPI:   0 = C[r,c] = acc + bias[c] (fp32, stride NP)
//        1 = LSTM, addend = pre[r*NP+c] (xproj)
//        2 = LSTM, addend = bias[c]
// Block: 64 rows x 128 cols, 256 threads = 8 warps (2m x 4n), warp tile 32x32.
__device__ __forceinline__ void mma_bf16(float* c, const uint32_t* a, const uint32_t* b) {
    asm volatile(
        "mma.sync.aligned.m16n8k16.row.col.f32.bf16.bf16.f32 "
        "{%0,%1,%2,%3}, {%4,%5,%6,%7}, {%8,%9}, {%0,%1,%2,%3};\n"
        : "+f"(c[0]), "+f"(c[1]), "+f"(c[2]), "+f"(c[3])
        : "r"(a[0]), "r"(a[1]), "r"(a[2]), "r"(a[3]), "r"(b[0]), "r"(b[1]));
}

template<int AMODE, int EPI>
__global__ void __launch_bounds__(256) mma_gemm(
    const __nv_bfloat16* __restrict__ Ah, const __nv_bfloat16* __restrict__ Al,
    const __nv_bfloat16* __restrict__ A2h, const __nv_bfloat16* __restrict__ A2l,
    const __nv_bfloat16* __restrict__ Bh, const __nv_bfloat16* __restrict__ Bl,
    const float* __restrict__ pre, const float* __restrict__ bias,
    float* __restrict__ C, float* __restrict__ cSt, float* __restrict__ hOut,
    __nv_bfloat16* __restrict__ hOh, __nv_bfloat16* __restrict__ hOl,
    int K, int lda)
{
    // staging arrays are raw uint16_t (bit-cast bf16) -> POD union, no ctor issues
    struct S {
        uint16_t Ah_[64][40], Al_[64][40];    // rows 80B (16B-aligned), +8 pad
        uint16_t Bh_[128][40], Bl_[128][40];  // transposed weight tile [n][k]
    };
    union U { S s; float Gs[64][132]; };      // Gs aliases staging after mainloop
    __shared__ __align__(16) U u;

    const int tid  = threadIdx.x;
    const int lane = tid & 31, warp = tid >> 5;
    const int quad = lane >> 2, tq = lane & 3;
    const int mw   = warp >> 2, nw = warp & 3;     // 2 x 4 warp grid
    const int rowBase = blockIdx.y * 64, colBase = blockIdx.x * 128;

    const int ar = tid >> 2, aseg = tid & 3;       // A staging: 64 rows x 4 segs of 8 bf16
    const int bn = tid >> 1, bseg = tid & 1;       // B staging: 128 rows x 2 segs of 16 bf16

    float acc[2][4][4];
#pragma unroll
    for (int mi = 0; mi < 2; mi++)
#pragma unroll
        for (int ni = 0; ni < 4; ni++)
#pragma unroll
            for (int x = 0; x < 4; x++) acc[mi][ni][x] = 0.f;

    uint4 rA[2], rB[2][2];

    auto fetch = [&](int k0) {
        int kk = k0 + aseg * 8;
        const __nv_bfloat16* ph = Ah; const __nv_bfloat16* pl = Al;
        if (AMODE == 2 && kk >= HP) { ph = A2h; pl = A2l; kk -= HP; }
        size_t aoff = (size_t)(rowBase + ar) * lda + kk;
        rA[0] = *reinterpret_cast<const uint4*>(ph + aoff);
        rA[1] = *reinterpret_cast<const uint4*>(pl + aoff);
        size_t boff = (size_t)(colBase + bn) * K + k0 + bseg * 16;
        rB[0][0] = *reinterpret_cast<const uint4*>(Bh + boff);
        rB[0][1] = *reinterpret_cast<const uint4*>(Bh + boff + 8);
        rB[1][0] = *reinterpret_cast<const uint4*>(Bl + boff);
        rB[1][1] = *reinterpret_cast<const uint4*>(Bl + boff + 8);
    };
    auto stage = [&]() {
        *reinterpret_cast<uint4*>(&u.s.Ah_[ar][aseg * 8]) = rA[0];
        *reinterpret_cast<uint4*>(&u.s.Al_[ar][aseg * 8]) = rA[1];
        *reinterpret_cast<uint4*>(&u.s.Bh_[bn][bseg * 16])     = rB[0][0];
        *reinterpret_cast<uint4*>(&u.s.Bh_[bn][bseg * 16 + 8]) = rB[0][1];
        *reinterpret_cast<uint4*>(&u.s.Bl_[bn][bseg * 16])     = rB[1][0];
        *reinterpret_cast<uint4*>(&u.s.Bl_[bn][bseg * 16 + 8]) = rB[1][1];
    };

    fetch(0);
    for (int k0 = 0; k0 < K; k0 += 32) {
        stage();
        __syncthreads();
        if (k0 + 32 < K) fetch(k0 + 32);   // prefetch next tile during compute
#pragma unroll
        for (int kb = 0; kb < 32; kb += 16) {
            uint32_t afh[2][4], afl[2][4], bfh[4][2], bfl[4][2];
#pragma unroll
            for (int mi = 0; mi < 2; mi++) {
                int r0 = mw * 32 + mi * 16 + quad;
                afh[mi][0] = *reinterpret_cast<const uint32_t*>(&u.s.Ah_[r0][kb + tq * 2]);
                afh[mi][1] = *reinterpret_cast<const uint32_t*>(&u.s.Ah_[r0 + 8][kb + tq * 2]);
                afh[mi][2] = *reinterpret_cast<const uint32_t*>(&u.s.Ah_[r0][kb + tq * 2 + 8]);
                afh[mi][3] = *reinterpret_cast<const uint32_t*>(&u.s.Ah_[r0 + 8][kb + tq * 2 + 8]);
                afl[mi][0] = *reinterpret_cast<const uint32_t*>(&u.s.Al_[r0][kb + tq * 2]);
                afl[mi][1] = *reinterpret_cast<const uint32_t*>(&u.s.Al_[r0 + 8][kb + tq * 2]);
                afl[mi][2] = *reinterpret_cast<const uint32_t*>(&u.s.Al_[r0][kb + tq * 2 + 8]);
                afl[mi][3] = *reinterpret_cast<const uint32_t*>(&u.s.Al_[r0 + 8][kb + tq * 2 + 8]);
            }
#pragma unroll
            for (int ni = 0; ni < 4; ni++) {
                int n0 = nw * 32 + ni * 8 + quad;
                bfh[ni][0] = *reinterpret_cast<const uint32_t*>(&u.s.Bh_[n0][kb + tq * 2]);
                bfh[ni][1] = *reinterpret_cast<const uint32_t*>(&u.s.Bh_[n0][kb + tq * 2 + 8]);
                bfl[ni][0] = *reinterpret_cast<const uint32_t*>(&u.s.Bl_[n0][kb + tq * 2]);
                bfl[ni][1] = *reinterpret_cast<const uint32_t*>(&u.s.Bl_[n0][kb + tq * 2 + 8]);
            }
#pragma unroll
            for (int mi = 0; mi < 2; mi++)
#pragma unroll
                for (int ni = 0; ni < 4; ni++) {
                    mma_bf16(acc[mi][ni], afh[mi], bfh[ni]);   // hi*hi
                    mma_bf16(acc[mi][ni], afh[mi], bfl[ni]);   // hi*lo
                    mma_bf16(acc[mi][ni], afl[mi], bfh[ni]);   // lo*hi
                }
        }
        __syncthreads();
    }

    // accumulators -> Gs (aliases staging; safe after the trailing syncthreads)
#pragma unroll
    for (int mi = 0; mi < 2; mi++)
#pragma unroll
        for (int ni = 0; ni < 4; ni++) {
            int r = mw * 32 + mi * 16 + quad, c = nw * 32 + ni * 8 + tq * 2;
            u.Gs[r][c]     = acc[mi][ni][0]; u.Gs[r][c + 1]     = acc[mi][ni][1];
            u.Gs[r + 8][c] = acc[mi][ni][2]; u.Gs[r + 8][c + 1] = acc[mi][ni][3];
        }
    __syncthreads();

    // epilogue: 64x128 tile = 2048 gate-groups of 4; 8 per thread
#pragma unroll
    for (int i = 0; i < 8; i++) {
        int id = tid + i * 256;
        int rr = id >> 5, uu = id & 31;
        int r = rowBase + rr;
        int cg = colBase + uu * 4;
        float4 g = *reinterpret_cast<const float4*>(&u.Gs[rr][uu * 4]);
        if (EPI == 0) {
            float4 b = *reinterpret_cast<const float4*>(&bias[cg]);
            float4 o; o.x = g.x + b.x; o.y = g.y + b.y; o.z = g.z + b.z; o.w = g.w + b.w;
            *reinterpret_cast<float4*>(&C[(size_t)r * NP + cg]) = o;
        } else {
            float4 ad;
            if (EPI == 1) ad = *reinterpret_cast<const float4*>(&pre[(size_t)r * NP + cg]);
            else          ad = *reinterpret_cast<const float4*>(&bias[cg]);
            float gi = g.x + ad.x, gf = g.y + ad.y, gg = g.z + ad.z, go = g.w + ad.w;
            int off = r * HP + (cg >> 2);
            float cold = cSt[off];
            float I = sigm(gi), Fg = sigm(gf), G = tanhf(gg), O = sigm(go);
            float cn = Fg * cold + I * G;
            float hn = O * tanhf(cn);
            cSt[off] = cn; hOut[off] = hn;
            __nv_bfloat16 hh, hl; bsplit(hn, hh, hl);
            hOh[off] = hh; hOl[off] = hl;
        }
    }
}

// ---------------- fp32 FFMA tail GEMM (audited R2 version, bias epilogue) ----------------
template<int BM, int BN, int BK, int TM, int TN>
__global__ void gemm_tail(const float* __restrict__ A, const float* __restrict__ Bm,
                          const float* __restrict__ bias, float* __restrict__ C,
                          int K, int lda, int ldb, int ldc) {
    __shared__ float As[BK][BM + 4];
    __shared__ float Bs[BK][BN];
    const int NT = (BM / TM) * (BN / TN);   // 256
    const int LA = (BM * BK) / 256, LB = (BK * BN) / 256;
    const int tid = threadIdx.x;
    const int tx = tid % (BN / TN), ty = tid / (BN / TN);
    const int rowBase = blockIdx.y * BM, colBase = blockIdx.x * BN;

    float acc[TM][TN];
#pragma unroll
    for (int i = 0; i < TM; i++)
#pragma unroll
        for (int j = 0; j < TN; j++) acc[i][j] = 0.f;

    float ra[LA], rb[LB];
    auto fetch = [&](int k0) {
#pragma unroll
        for (int i = 0; i < LA; i++) {
            int e = tid + i * NT;
            ra[i] = A[(rowBase + e / BK) * lda + k0 + e % BK];
        }
#pragma unroll
        for (int i = 0; i < LB; i++) {
            int e = tid + i * NT;
            rb[i] = Bm[(k0 + e / BN) * ldb + colBase + e % BN];
        }
    };
    auto stage = [&]() {
#pragma unroll
        for (int i = 0; i < LA; i++) { int e = tid + i * NT; As[e % BK][e / BK] = ra[i]; }
#pragma unroll
        for (int i = 0; i < LB; i++) { int e = tid + i * NT; Bs[e / BN][e % BN] = rb[i]; }
    };

    fetch(0);
    for (int k0 = 0; k0 < K; k0 += BK) {
        stage();
        __syncthreads();
        if (k0 + BK < K) fetch(k0 + BK);
#pragma unroll
        for (int kk = 0; kk < BK; kk++) {
            float a[TM], b[TN];
#pragma unroll
            for (int i = 0; i < TM; i++) a[i] = As[kk][ty * TM + i];
#pragma unroll
            for (int j = 0; j < TN; j++) b[j] = Bs[kk][tx * TN + j];
#pragma unroll
            for (int i = 0; i < TM; i++)
#pragma unroll
                for (int j = 0; j < TN; j++) acc[i][j] += a[i] * b[j];
        }
        __syncthreads();
    }
#pragma unroll
    for (int i = 0; i < TM; i++) {
        int r = rowBase + ty * TM + i;
#pragma unroll
        for (int j = 0; j < TN; j++) {
            int c = colBase + tx * TN + j;
            C[r * ldc + c] = acc[i][j] + bias[c];
        }
    }
}

// ---------------- Tail kernels ----------------
__global__ void k_buildF(const float* __restrict__ h1fin) {
    int idx = blockIdx.x * blockDim.x + threadIdx.x;
    if (idx >= BB * 2 * HP) return;
    int m = idx / (2 * HP), k = idx % (2 * HP);
    g_F[idx] = (k < HP) ? h1fin[m * HP + k] : 0.f;
}
__global__ void k_scatterTopic(const int* __restrict__ hidx) {
    int m = threadIdx.x;
    if (m >= BB) return;
#pragma unroll
    for (int j = 0; j < 5; j++) {
        int u = hidx[m * 5 + j];
        g_F[m * 2 * HP + HP + u] = 1.0f;
    }
}
__global__ void k_softmax(float* __restrict__ out, int out_size) {
    int j = blockIdx.x, r = threadIdx.x;
    __shared__ float sm[256];
    float v = g_m2[r * HP + j];
    sm[r] = v; __syncthreads();
    for (int s = 128; s > 0; s >>= 1) { if (r < s) sm[r] = fmaxf(sm[r], sm[r + s]); __syncthreads(); }
    float mx = sm[0]; __syncthreads();
    float e = expf(v - mx);
    sm[r] = e; __syncthreads();
    for (int s = 128; s > 0; s >>= 1) { if (r < s) sm[r] += sm[r + s]; __syncthreads(); }
    float p = e / sm[0];
    int off = r * 1000 + j;
    if (off < out_size) out[off] = p;
}
__global__ void k_copyStates(float* __restrict__ out, int out_size) {
    int idx = blockIdx.x * blockDim.x + threadIdx.x;
    if (idx >= 4 * BB * H) return;
    int which = idx / (BB * H), rem = idx % (BB * H);
    int m = rem / H, u = rem % H;
    const float* src;
    if (which == 0)      src = g_h1f[0];
    else if (which == 1) src = g_c1;
    else if (which == 2) src = g_h2f[0];
    else                 src = g_c2;
    int off = BB * H + idx;
    if (off < out_size) out[off] = src[m * HP + u];
}

// ---------------- Launch ----------------
extern "C" void kernel_launch(void* const* d_in, const int* in_sizes, int n_in,
                              void* d_out, int out_size) {
    const float* input = (const float*)d_in[0];
    const int*   hidx  = (const int*)d_in[1];
    const float* Wih1  = (const float*)d_in[2];
    const float* Whh1  = (const float*)d_in[3];
    const float* bih1  = (const float*)d_in[4];
    const float* bhh1  = (const float*)d_in[5];
    const float* Wih2  = (const float*)d_in[6];
    const float* Whh2  = (const float*)d_in[7];
    const float* bih2  = (const float*)d_in[8];
    const float* bhh2  = (const float*)d_in[9];
    const float* W1    = (const float*)d_in[10];
    const float* b1    = (const float*)d_in[11];
    const float* W2    = (const float*)d_in[12];
    const float* b2    = (const float*)d_in[13];
    float* out = (float*)d_out;

    __nv_bfloat16 *pWA1h, *pWA1l, *pWB1h, *pWB1l, *pWC2h, *pWC2l, *pih, *pil;
    __nv_bfloat16 *ph1bh, *ph1bl, *ph2bh, *ph2bl;
    float *pW1T, *pW2T, *pb1v, *pb2v, *pbl1, *pbl2, *pxp;
    float *ph1f, *ph2f, *pc1, *pc2, *pF, *pm1, *pm2;
    cudaGetSymbolAddress((void**)&pWA1h, g_WA1h);  cudaGetSymbolAddress((void**)&pWA1l, g_WA1l);
    cudaGetSymbolAddress((void**)&pWB1h, g_WB1h);  cudaGetSymbolAddress((void**)&pWB1l, g_WB1l);
    cudaGetSymbolAddress((void**)&pWC2h, g_WC2h);  cudaGetSymbolAddress((void**)&pWC2l, g_WC2l);
    cudaGetSymbolAddress((void**)&pih,   g_ih);    cudaGetSymbolAddress((void**)&pil,   g_il);
    cudaGetSymbolAddress((void**)&pW1T,  g_W1T);   cudaGetSymbolAddress((void**)&pW2T,  g_W2T);
    cudaGetSymbolAddress((void**)&pb1v,  g_b1v);   cudaGetSymbolAddress((void**)&pb2v,  g_b2v);
    cudaGetSymbolAddress((void**)&pbl1,  g_bl1);   cudaGetSymbolAddress((void**)&pbl2,  g_bl2);
    cudaGetSymbolAddress((void**)&pxp,   g_xproj);
    cudaGetSymbolAddress((void**)&ph1f,  g_h1f);   cudaGetSymbolAddress((void**)&ph2f,  g_h2f);
    cudaGetSymbolAddress((void**)&pc1,   g_c1);    cudaGetSymbolAddress((void**)&pc2,   g_c2);
    cudaGetSymbolAddress((void**)&ph1bh, g_h1bh);  cudaGetSymbolAddress((void**)&ph1bl, g_h1bl);
    cudaGetSymbolAddress((void**)&ph2bh, g_h2bh);  cudaGetSymbolAddress((void**)&ph2bl, g_h2bl);
    cudaGetSymbolAddress((void**)&pF,    g_F);
    cudaGetSymbolAddress((void**)&pm1,   g_m1);    cudaGetSymbolAddress((void**)&pm2,   g_m2);

    const int TH = 256;
    // 1) folds + input split
    k_foldWA1b<<<(NP * KA + TH - 1) / TH, TH>>>(Wih1);
    k_foldWB1b<<<(NP * HP + TH - 1) / TH, TH>>>(Wih1, Whh1);
    k_foldWC2b<<<(NP * 2 * HP + TH - 1) / TH, TH>>>(Wih2, Whh2);
    k_foldBias<<<(NP + TH - 1) / TH, TH>>>(bih1, bhh1, bih2, bhh2);
    k_foldW1T<<<(2 * HP * NP + TH - 1) / TH, TH>>>(W1);
    k_foldW2T<<<(NP * HP + TH - 1) / TH, TH>>>(W2);
    k_foldLinB<<<(NP + TH - 1) / TH, TH>>>(b1, b2);
    k_zeroState<<<(BB * HP + TH - 1) / TH, TH>>>();
    k_splitInput<<<(TT * BB * KA + TH - 1) / TH, TH>>>(input);

    // 2) Xproj = split(input) @ WA1^T + b1v   (M=16384, N=4096, K=640)
    mma_gemm<0, 0><<<dim3(NP / 128, (TT * BB) / 64), TH>>>(
        pih, pil, nullptr, nullptr, pWA1h, pWA1l, nullptr, pb1v,
        pxp, nullptr, nullptr, nullptr, nullptr, KA, KA);

    // 3) recurrent steps
    float* h1f[2] = { ph1f, ph1f + BB * HP };
    float* h2f[2] = { ph2f, ph2f + BB * HP };
    __nv_bfloat16* h1h[2] = { ph1bh, ph1bh + BB * HP };
    __nv_bfloat16* h1l[2] = { ph1bl, ph1bl + BB * HP };
    __nv_bfloat16* h2h[2] = { ph2bh, ph2bh + BB * HP };
    __nv_bfloat16* h2l[2] = { ph2bl, ph2bl + BB * HP };
    for (int t = 0; t < TT; t++) {
        int p = t & 1;
        dim3 grid(NP / 128, BB / 64);
        // LSTM1: gates = Xproj[t] + h1_old @ WB1  -> h1_new, c1
        mma_gemm<0, 1><<<grid, TH>>>(
            h1h[p], h1l[p], nullptr, nullptr, pWB1h, pWB1l,
            pxp + (size_t)t * BB * NP, nullptr,
            nullptr, pc1, h1f[1 - p], h1h[1 - p], h1l[1 - p], HP, HP);
        // LSTM2: gates = b2v + [h1_new | h2_old] @ WC2 -> h2_new, c2
        mma_gemm<2, 2><<<grid, TH>>>(
            h1h[1 - p], h1l[1 - p], h2h[p], h2l[p], pWC2h, pWC2l,
            nullptr, pb2v,
            nullptr, pc2, h2f[1 - p], h2h[1 - p], h2l[1 - p], 2 * HP, HP);
    }
    // after 64 steps (even), final states in buffer 0

    // 4) tail (fp32 FFMA to protect logit precision)
    k_buildF<<<(BB * 2 * HP + TH - 1) / TH, TH>>>(h1f[0]);
    k_scatterTopic<<<1, TH>>>(hidx);
    gemm_tail<64, 128, 16, 4, 8><<<dim3(NP / 128, BB / 64), TH>>>(
        pF, pW1T, pbl1, pm1, 2 * HP, 2 * HP, NP, NP);
    gemm_tail<32, 64, 16, 2, 4><<<dim3(HP / 64, BB / 32), TH>>>(
        pm1, pW2T, pbl2, pm2, NP, NP, HP, HP);

    // 5) softmax over batch (axis 0) + emit states
    k_softmax<<<1000, 256>>>(out, out_size);
    k_copyStates<<<(4 * BB * H + TH - 1) / TH, TH>>>(out, out_size);
}